// round 15
// baseline (speedup 1.0000x reference)
#include <cuda_runtime.h>
#include <cuda_bf16.h>
#include <cstdint>

// ---------------- problem dims ----------------
#define SEQT  512
#define IDIM  64
#define HDIM  256
#define XSTR  ((size_t)SEQT * IDIM)

// ---------------- tiling ----------------
#define CLUSTER 8        // CTAs per cluster: each owns 32 hidden units
#define NBG     8        // batch groups (clusters); 64 rows each = 4 streams x 16
#define NSTR    4        // independent recurrence streams per CTA
#define MTG     16       // batch rows per stream
#define NTH     512      // 16 warps: 4 per stream
#define PB      336      // weight row pitch in bf16 (336 % 64 == 16 -> conflict-free)
#define ROWB    (PB * 2) // 672 bytes per weight row
#define WROWS   128      // gate rows per CTA: 4 chains (r,z,nh,nx) x 32 units
#define WBYTES  (WROWS * ROWB)          // 86016 (multiple of 512)
#define SLAB    512
#define ABUF    (20 * SLAB)             // 10240 per [stream][parity] buffer
#define SMEMSZ  (WBYTES + 2 * NSTR * ABUF)   // 167936
#define TXB     (7 * 1024)              // bulk-tx bytes expected per stream phase

// within-16-col fragment order: elem e -> byte offset in a 32B row
__device__ __forceinline__ int pos16(int e) {
    return ((e >> 1) & 3) * 8 + ((e >> 3) << 2) + (e & 1) * 2;
}
// weight-side perm across full k (same order per 16-block)
__device__ __forceinline__ int perm(int k) {
    int j = k & 15;
    return (k & ~15) + ((j >> 1) & 3) * 4 + ((j >> 3) << 1) + (j & 1);
}

__device__ __forceinline__ float sigf(float v) { return 1.0f / (1.0f + __expf(-v)); }
__device__ __forceinline__ float tanh_acc(float v) {
    v = fminf(fmaxf(v, -10.f), 10.f);
    float e = __expf(-2.f * v);
    return __fdividef(1.f - e, 1.f + e);
}

__device__ __forceinline__ uint32_t smem_u32(const void* p) {
    uint32_t a;
    asm("{ .reg .u64 t; cvta.to.shared.u64 t, %1; cvt.u32.u64 %0, t; }" : "=r"(a) : "l"(p));
    return a;
}
__device__ __forceinline__ uint32_t pack_bf16x2(float lo, float hi) {
    uint32_t r;
    asm("cvt.rn.bf16x2.f32 %0, %1, %2;" : "=r"(r) : "f"(hi), "f"(lo));
    return r;
}
__device__ __forceinline__ void lds2(uint32_t& x, uint32_t& y, uint32_t addr) {
    asm volatile("ld.shared.v2.b32 {%0, %1}, [%2];" : "=r"(x), "=r"(y) : "r"(addr));
}
__device__ __forceinline__ uint32_t mapa_u32(uint32_t laddr, int rank) {
    uint32_t r;
    asm("mapa.shared::cluster.u32 %0, %1, %2;" : "=r"(r) : "r"(laddr), "r"(rank));
    return r;
}
__device__ __forceinline__ void bulk_to_peer(uint32_t dst_cluster, uint32_t src_cta,
                                             uint32_t bytes, uint32_t rmbar) {
    asm volatile("cp.async.bulk.shared::cluster.shared::cta.mbarrier::complete_tx::bytes "
                 "[%0], [%1], %2, [%3];"
                 :: "r"(dst_cluster), "r"(src_cta), "r"(bytes), "r"(rmbar) : "memory");
}
#define MBARRIER_INIT(mb, c) \
    asm volatile("mbarrier.init.shared.b64 [%0], %1;" \
                 :: "r"((uint32_t)(mb)), "r"((uint32_t)(c)) : "memory")
#define MBARRIER_ARRIVE_EXPECT_TX(mb, n) \
    asm volatile("mbarrier.arrive.expect_tx.shared.b64 _, [%0], %1;" \
                 :: "r"((uint32_t)(mb)), "r"((uint32_t)(n)) : "memory")
#define MBARRIER_WAIT_PARITY(mb, par) do { \
    uint32_t _m = (uint32_t)(mb), _p = (uint32_t)(par), _d; \
    asm volatile("{\n\t.reg .pred p;\n\t" \
        "mbarrier.try_wait.parity.acquire.cta.shared::cta.b64 p, [%1], %2;\n\t" \
        "selp.b32 %0, 1, 0, p;\n\t}" : "=r"(_d) : "r"(_m), "r"(_p) : "memory"); \
    if (!_d) { \
        asm volatile("{\n\t.reg .pred P1;\n\t" \
            "WL_%=:\n\t" \
            "mbarrier.try_wait.parity.acquire.cta.shared::cta.b64 P1, [%0], %1, 0x989680;\n\t" \
            "@P1 bra.uni WD_%=;\n\tbra.uni WL_%=;\n\tWD_%=:\n\t}" \
            :: "r"(_m), "r"(_p) : "memory"); \
    } } while (0)
#define CLUSTER_SYNC() do { \
    asm volatile("barrier.cluster.arrive.aligned;" ::: "memory"); \
    asm volatile("barrier.cluster.wait.aligned;"   ::: "memory"); } while (0)
#define STREAM_BAR(id) \
    asm volatile("bar.sync %0, 128;" :: "r"(id) : "memory")

// D += A(16x16) * B(16x8)^T, bf16 -> f32
__device__ __forceinline__ void mma16(float* d, uint32_t a0, uint32_t a1, uint32_t a2,
                                      uint32_t a3, uint32_t b0, uint32_t b1) {
    asm volatile(
        "mma.sync.aligned.m16n8k16.row.col.f32.bf16.bf16.f32 "
        "{%0,%1,%2,%3}, {%4,%5,%6,%7}, {%8,%9}, {%0,%1,%2,%3};"
        : "+f"(d[0]), "+f"(d[1]), "+f"(d[2]), "+f"(d[3])
        : "r"(a0), "r"(a1), "r"(a2), "r"(a3), "r"(b0), "r"(b1));
}

__global__ void __launch_bounds__(NTH, 1) __cluster_dims__(CLUSTER, 1, 1)
gru_acc2(const float* __restrict__ x,      // [B, T, I]
         const float* __restrict__ w_ih,   // [3H, I]
         const float* __restrict__ w_hh,   // [3H, H]
         const float* __restrict__ b_ih,   // [3H]
         const float* __restrict__ b_hh,   // [3H]
         const float* __restrict__ w_lin,  // [1, H]
         const float* __restrict__ b_lin,  // [1]
         float* __restrict__ out)          // [2B]
{
    extern __shared__ char smem[];
    __shared__ __align__(8) uint64_t mbars[2 * NSTR];   // [stream][parity]
    const uint32_t sbase = smem_u32(smem);

    const int tid  = threadIdx.x;
    const int wid  = tid >> 5;
    const int lane = tid & 31;
    const int gw   = wid >> 2;         // stream 0..3
    const int oct  = wid & 3;          // unit octet within stream
    const int g    = lane >> 2;        // fragment row 0..7
    const int c    = lane & 3;         // fragment k-lane 0..3
    const int gtid = tid & 127;        // thread id within stream
    const int rank = blockIdx.x;       // cluster rank: units rank*32..+32
    const int bg   = blockIdx.y;       // batch group (rows bg*64..+64)

    // ---- zero all activation buffers (h(0)=0, pads clean) ----
    for (int e = tid; e < 2 * NSTR * ABUF / 4; e += NTH)
        *(uint32_t*)(smem + WBYTES + e * 4) = 0u;

    // ---- weights -> SMEM bf16, permuted. rows: chain*32+u; chains r,z,nh,nx ----
    for (int e = tid; e < WROWS * PB; e += NTH) {
        int row = e / PB, k = e - row * PB;
        int ch = row >> 5, u = row & 31, gu = rank * 32 + u;
        float v = 0.f;
        if (k < 320) {
            if (ch == 0) {
                v = (k < HDIM) ? w_hh[(size_t)gu * HDIM + k]
                               : w_ih[(size_t)gu * IDIM + (k - HDIM)];
            } else if (ch == 1) {
                int gr = HDIM + gu;
                v = (k < HDIM) ? w_hh[(size_t)gr * HDIM + k]
                               : w_ih[(size_t)gr * IDIM + (k - HDIM)];
            } else if (ch == 2) {
                if (k < HDIM) v = w_hh[(size_t)(2 * HDIM + gu) * HDIM + k];
            } else {
                if (k >= HDIM) v = w_ih[(size_t)(2 * HDIM + gu) * IDIM + (k - HDIM)];
            }
        }
        *(__nv_bfloat16*)(smem + row * ROWB + (k < 320 ? perm(k) : k) * 2) =
            __float2bfloat16(v);
    }

    // ---- per-thread biases for my 2 units ----
    const int u0 = oct * 8 + 2 * c;
    float bR[2], bZ[2], bIN[2], bHN[2];
#pragma unroll
    for (int j = 0; j < 2; j++) {
        int gu = rank * 32 + u0 + j;
        bR[j]  = b_ih[gu] + b_hh[gu];
        bZ[j]  = b_ih[HDIM + gu] + b_hh[HDIM + gu];
        bIN[j] = b_ih[2 * HDIM + gu];
        bHN[j] = b_hh[2 * HDIM + gu];
    }

    // ---- stage x(0) into buffer [gw][0], slabs 16..19 ----
    const float* xgrp = x + (size_t)(bg * (NSTR * MTG) + gw * MTG) * XSTR;
    {
        const uint32_t b0 = WBYTES + (uint32_t)(gw * 2) * ABUF;
#pragma unroll
        for (int q = 0; q < 2; q++) {
            int fi = gtid + q * 128;
            int row = fi >> 4, c4 = fi & 15;
            int kb = 16 + (c4 >> 2), m = c4 & 3;
            float4 v = __ldg((const float4*)(xgrp + (size_t)row * XSTR + c4 * 4));
            char* slab = smem + b0 + kb * SLAB + row * 32;
            *(uint32_t*)(slab + pos16(4 * m))     = pack_bf16x2(v.x, v.y);
            *(uint32_t*)(slab + pos16(4 * m + 2)) = pack_bf16x2(v.z, v.w);
        }
    }
    if (tid == 0) {
#pragma unroll
        for (int i = 0; i < 2 * NSTR; i++) MBARRIER_INIT(smem_u32(&mbars[i]), 1);
    }
    __syncthreads();

    // ---- per-warp addresses ----
    const uint32_t abuf_s = sbase + WBYTES;
    const uint32_t aoff = (uint32_t)g * 32 + 8u * c;           // + bi*ABUF + kb*SLAB
    const uint32_t bR_a = sbase + (uint32_t)(oct * 8 + g) * ROWB + 8u * c;
    const uint32_t bZ_a = bR_a + 32u * ROWB;
    const uint32_t bH_a = bR_a + 64u * ROWB;
    const uint32_t bX_a = bR_a + 96u * ROWB;

    // ---- hoist nh weight fragments into registers (step-invariant) ----
    uint32_t wNH[16][2];
#pragma unroll
    for (int kb = 0; kb < 16; kb++) lds2(wNH[kb][0], wNH[kb][1], bH_a + kb * 32u);

    CLUSTER_SYNC();   // mbarriers + buffers visible cluster-wide before any bulk copy

    float hprev[4] = {0.f, 0.f, 0.f, 0.f};
    int ph[2] = {0, 0};
    const uint32_t mb_s = smem_u32(&mbars[gw * 2]);      // my stream's 2 mbars
    const int peer = (gtid < 7) ? (gtid < rank ? gtid : gtid + 1) : 0;
    const uint32_t myslab_off = (uint32_t)(2 * rank) * SLAB;
    const uint32_t est = ((u0 >> 4) ? SLAB : 0) + (uint32_t)g * 32 + (uint32_t)pos16(u0 & 15);

#pragma unroll 1
    for (int t = 0; t < SEQT; ++t) {
        const uint32_t npar = (t + 1) & 1;
        const uint32_t nb_off = WBYTES + (uint32_t)(gw * 2 + npar) * ABUF;
        const uint32_t acur = abuf_s + (uint32_t)(gw * 2 + (t & 1)) * ABUF + aoff;

        // ---- stage x(t+1) (pre-wait; stream-local slabs, sequenced by last bar) ----
        if (t + 1 < SEQT) {
#pragma unroll
            for (int q = 0; q < 2; q++) {
                int fi = gtid + q * 128;
                int row = fi >> 4, c4 = fi & 15;
                int kb = 16 + (c4 >> 2), m = c4 & 3;
                float4 v = __ldg((const float4*)(xgrp + (size_t)row * XSTR
                                                 + (size_t)(t + 1) * IDIM + c4 * 4));
                char* slab = smem + nb_off + kb * SLAB + row * 32;
                *(uint32_t*)(slab + pos16(4 * m))     = pack_bf16x2(v.x, v.y);
                *(uint32_t*)(slab + pos16(4 * m + 2)) = pack_bf16x2(v.z, v.w);
            }
        }

        // ---- pre-wait x-part MMA (kb 16..19; r,z,nx weights from smem) ----
        float dR[4] = {0, 0, 0, 0}, dZ[4] = {0, 0, 0, 0};
        float dH[4] = {0, 0, 0, 0}, dX[4] = {0, 0, 0, 0};
#pragma unroll
        for (int kb = 16; kb < 20; kb++) {
            const uint32_t ao = acur + (uint32_t)kb * SLAB;
            const uint32_t wo = (uint32_t)kb * 32u;
            uint32_t a0, a2, a1, a3, r0, r1, z0, z1, n0, n1;
            lds2(a0, a2, ao);
            lds2(a1, a3, ao + 256);
            lds2(r0, r1, bR_a + wo);
            lds2(z0, z1, bZ_a + wo);
            lds2(n0, n1, bX_a + wo);
            mma16(dR, a0, a1, a2, a3, r0, r1);
            mma16(dZ, a0, a1, a2, a3, z0, z1);
            mma16(dX, a0, a1, a2, a3, n0, n1);
        }

        // ---- wait for h(t) ----
        if (t > 0) {
            int m = t & 1;
            MBARRIER_WAIT_PARITY(mb_s + 8u * m, ph[m]);
            ph[m] ^= 1;

            // ---- post-wait h-part MMA (kb 0..15), 2-way split accumulators:
            //      even kb -> dR/dZ/dH, odd kb -> dRb/dZb/dHb (chain depth 16->8) ----
            float dRb[4] = {0, 0, 0, 0}, dZb[4] = {0, 0, 0, 0}, dHb[4] = {0, 0, 0, 0};
#pragma unroll
            for (int kb = 0; kb < 16; kb++) {
                const uint32_t ao = acur + (uint32_t)kb * SLAB;
                const uint32_t wo = (uint32_t)kb * 32u;
                uint32_t a0, a2, a1, a3, r0, r1, z0, z1;
                lds2(a0, a2, ao);
                lds2(a1, a3, ao + 256);
                lds2(r0, r1, bR_a + wo);
                lds2(z0, z1, bZ_a + wo);
                if ((kb & 1) == 0) {
                    mma16(dR, a0, a1, a2, a3, r0, r1);
                    mma16(dZ, a0, a1, a2, a3, z0, z1);
                    mma16(dH, a0, a1, a2, a3, wNH[kb][0], wNH[kb][1]);
                } else {
                    mma16(dRb, a0, a1, a2, a3, r0, r1);
                    mma16(dZb, a0, a1, a2, a3, z0, z1);
                    mma16(dHb, a0, a1, a2, a3, wNH[kb][0], wNH[kb][1]);
                }
            }
#pragma unroll
            for (int i = 0; i < 4; i++) {
                dR[i] += dRb[i];
                dZ[i] += dZb[i];
                dH[i] += dHb[i];
            }
        }

        // ---- gate epilogue (register-local; exact fp32 hprev) ----
        float hn[4];
#pragma unroll
        for (int i = 0; i < 4; i++) {
            int j = i & 1;
            float r = sigf(dR[i] + bR[j]);
            float z = sigf(dZ[i] + bZ[j]);
            float n = tanh_acc(dX[i] + bIN[j] + r * (dH[i] + bHN[j]));
            hn[i] = fmaf(z, hprev[i] - n, n);
            hprev[i] = hn[i];
        }

        // ---- local STS of my h slab block, stream barrier ----
        {
            char* dst = smem + nb_off + myslab_off + est;
            *(uint32_t*)(dst)       = pack_bf16x2(hn[0], hn[1]);   // row g
            *(uint32_t*)(dst + 256) = pack_bf16x2(hn[2], hn[3]);   // row g+8
        }
        STREAM_BAR(1 + gw);

        // ---- exchange: 7 bulk copies (1KB each); SINGLE arrival (count=1).
        //      Read-safety via tx chain (see R12 derivation). ----
        const uint32_t lmb = mb_s + 8u * npar;
        if (gtid < 7) {
            asm volatile("fence.proxy.async.shared::cta;" ::: "memory");
            uint32_t src = sbase + nb_off + myslab_off;
            uint32_t dst = mapa_u32(src, peer);
            uint32_t rmb = mapa_u32(lmb, peer);
            bulk_to_peer(dst, src, 1024u, rmb);
        }
        if (gtid == 0) { MBARRIER_ARRIVE_EXPECT_TX(lmb, TXB); }
    }

    // ---- final wait: h(512) fully delivered into buffer [gw][0] ----
    MBARRIER_WAIT_PARITY(mb_s, ph[0]);

    // ---- head (rank 0): p = sigmoid(h_last . w_lin + b_lin); out = [p, 1-p] ----
    if (rank == 0) {
        const int row = gtid >> 3, seg = gtid & 7;
        const uint32_t hb = WBYTES + (uint32_t)(gw * 2) * ABUF;
        float s = 0.f;
#pragma unroll
        for (int kk = 0; kk < 32; kk++) {
            int k = seg * 32 + kk;
            const char* p8 = smem + hb + (k >> 4) * SLAB + row * 32 + pos16(k & 15);
            float hv = __bfloat162float(*(const __nv_bfloat16*)p8);
            s = fmaf(hv, __ldg(w_lin + k), s);
        }
        s += __shfl_xor_sync(0xffffffffu, s, 1);
        s += __shfl_xor_sync(0xffffffffu, s, 2);
        s += __shfl_xor_sync(0xffffffffu, s, 4);
        if (seg == 0) {
            float p = sigf(s + __ldg(b_lin));
            int gb = bg * (NSTR * MTG) + gw * MTG + row;
            out[2 * gb]     = p;
            out[2 * gb + 1] = 1.f - p;
        }
    }

    CLUSTER_SYNC();   // no CTA exits while peers may still target its SMEM
}

extern "C" void kernel_launch(void* const* d_in, const int* in_sizes, int n_in,
                              void* d_out, int out_size) {
    const float* x     = (const float*)d_in[0];
    const float* w_ih0 = (const float*)d_in[1];
    const float* w_hh0 = (const float*)d_in[2];
    const float* b_ih0 = (const float*)d_in[3];
    const float* b_hh0 = (const float*)d_in[4];
    // d_in[5..8]: layer-1 GRU weights — dead code (output uses layer-0 h_last only)
    const float* w_lin = (const float*)d_in[9];
    const float* b_lin = (const float*)d_in[10];
    float* out = (float*)d_out;

    cudaFuncSetAttribute(gru_acc2, cudaFuncAttributeMaxDynamicSharedMemorySize, SMEMSZ);

    dim3 grid(CLUSTER, NBG);   // 8 x 8 = 64 CTAs = 8 clusters of 8, 4 streams each
    gru_acc2<<<grid, NTH, SMEMSZ>>>(x, w_ih0, w_hh0, b_ih0, b_hh0, w_lin, b_lin, out);
}

// round 16
// speedup vs baseline: 1.2566x; 1.2566x over previous
#include <cuda_runtime.h>
#include <cuda_bf16.h>
#include <cstdint>

// ---------------- problem dims ----------------
#define SEQT  512
#define IDIM  64
#define HDIM  256
#define XSTR  ((size_t)SEQT * IDIM)

// ---------------- tiling ----------------
#define CLUSTER 8        // CTAs per cluster: each owns 32 hidden units
#define NBG     8        // batch groups (clusters); 64 rows each = 4 streams x 16
#define NSTR    4        // independent recurrence streams per CTA
#define MTG     16       // batch rows per stream
#define NTH     512      // 16 warps: 4 per stream
#define PB      336      // weight row pitch in bf16 (336 % 64 == 16 -> conflict-free)
#define ROWB    (PB * 2) // 672 bytes per weight row
#define WROWS   128      // gate rows per CTA: 4 chains (r,z,nh,nx) x 32 units
#define WBYTES  (WROWS * ROWB)          // 86016 (multiple of 512)
#define SLAB    512
#define ABUF    (20 * SLAB)             // 10240 per [stream][parity] buffer
#define SMEMSZ  (WBYTES + 2 * NSTR * ABUF)   // 167936
#define TXB     (7 * 1024)              // bulk-tx bytes expected per stream phase

// within-16-col fragment order: elem e -> byte offset in a 32B row
__device__ __forceinline__ int pos16(int e) {
    return ((e >> 1) & 3) * 8 + ((e >> 3) << 2) + (e & 1) * 2;
}
// weight-side perm across full k (same order per 16-block)
__device__ __forceinline__ int perm(int k) {
    int j = k & 15;
    return (k & ~15) + ((j >> 1) & 3) * 4 + ((j >> 3) << 1) + (j & 1);
}

// r,z gates: sigmoid via MUFU tanh (1 MUFU + 2 FMA)
__device__ __forceinline__ float sig_ap(float v) {
    float y;
    asm("tanh.approx.f32 %0, %1;" : "=f"(y) : "f"(0.5f * v));
    return fmaf(y, 0.5f, 0.5f);
}
__device__ __forceinline__ float sigf(float v) { return 1.0f / (1.0f + __expf(-v)); }
// n gate: accurate tanh (enters h directly)
__device__ __forceinline__ float tanh_acc(float v) {
    v = fminf(fmaxf(v, -10.f), 10.f);
    float e = __expf(-2.f * v);
    return __fdividef(1.f - e, 1.f + e);
}

__device__ __forceinline__ uint32_t smem_u32(const void* p) {
    uint32_t a;
    asm("{ .reg .u64 t; cvta.to.shared.u64 t, %1; cvt.u32.u64 %0, t; }" : "=r"(a) : "l"(p));
    return a;
}
__device__ __forceinline__ uint32_t pack_bf16x2(float lo, float hi) {
    uint32_t r;
    asm("cvt.rn.bf16x2.f32 %0, %1, %2;" : "=r"(r) : "f"(hi), "f"(lo));
    return r;
}
__device__ __forceinline__ void lds2(uint32_t& x, uint32_t& y, uint32_t addr) {
    asm volatile("ld.shared.v2.b32 {%0, %1}, [%2];" : "=r"(x), "=r"(y) : "r"(addr));
}
__device__ __forceinline__ uint32_t mapa_u32(uint32_t laddr, int rank) {
    uint32_t r;
    asm("mapa.shared::cluster.u32 %0, %1, %2;" : "=r"(r) : "r"(laddr), "r"(rank));
    return r;
}
__device__ __forceinline__ void bulk_to_peer(uint32_t dst_cluster, uint32_t src_cta,
                                             uint32_t bytes, uint32_t rmbar) {
    asm volatile("cp.async.bulk.shared::cluster.shared::cta.mbarrier::complete_tx::bytes "
                 "[%0], [%1], %2, [%3];"
                 :: "r"(dst_cluster), "r"(src_cta), "r"(bytes), "r"(rmbar) : "memory");
}
#define MBARRIER_INIT(mb, c) \
    asm volatile("mbarrier.init.shared.b64 [%0], %1;" \
                 :: "r"((uint32_t)(mb)), "r"((uint32_t)(c)) : "memory")
#define MBARRIER_ARRIVE_EXPECT_TX(mb, n) \
    asm volatile("mbarrier.arrive.expect_tx.shared.b64 _, [%0], %1;" \
                 :: "r"((uint32_t)(mb)), "r"((uint32_t)(n)) : "memory")
#define MBARRIER_WAIT_PARITY(mb, par) do { \
    uint32_t _m = (uint32_t)(mb), _p = (uint32_t)(par), _d; \
    asm volatile("{\n\t.reg .pred p;\n\t" \
        "mbarrier.try_wait.parity.acquire.cta.shared::cta.b64 p, [%1], %2;\n\t" \
        "selp.b32 %0, 1, 0, p;\n\t}" : "=r"(_d) : "r"(_m), "r"(_p) : "memory"); \
    if (!_d) { \
        asm volatile("{\n\t.reg .pred P1;\n\t" \
            "WL_%=:\n\t" \
            "mbarrier.try_wait.parity.acquire.cta.shared::cta.b64 P1, [%0], %1, 0x989680;\n\t" \
            "@P1 bra.uni WD_%=;\n\tbra.uni WL_%=;\n\tWD_%=:\n\t}" \
            :: "r"(_m), "r"(_p) : "memory"); \
    } } while (0)
#define CLUSTER_SYNC() do { \
    asm volatile("barrier.cluster.arrive.aligned;" ::: "memory"); \
    asm volatile("barrier.cluster.wait.aligned;"   ::: "memory"); } while (0)
#define STREAM_BAR(id) \
    asm volatile("bar.sync %0, 128;" :: "r"(id) : "memory")

// D += A(16x16) * B(16x8)^T, bf16 -> f32
__device__ __forceinline__ void mma16(float* d, uint32_t a0, uint32_t a1, uint32_t a2,
                                      uint32_t a3, uint32_t b0, uint32_t b1) {
    asm volatile(
        "mma.sync.aligned.m16n8k16.row.col.f32.bf16.bf16.f32 "
        "{%0,%1,%2,%3}, {%4,%5,%6,%7}, {%8,%9}, {%0,%1,%2,%3};"
        : "+f"(d[0]), "+f"(d[1]), "+f"(d[2]), "+f"(d[3])
        : "r"(a0), "r"(a1), "r"(a2), "r"(a3), "r"(b0), "r"(b1));
}

__global__ void __launch_bounds__(NTH, 1) __cluster_dims__(CLUSTER, 1, 1)
gru_tune(const float* __restrict__ x,      // [B, T, I]
         const float* __restrict__ w_ih,   // [3H, I]
         const float* __restrict__ w_hh,   // [3H, H]
         const float* __restrict__ b_ih,   // [3H]
         const float* __restrict__ b_hh,   // [3H]
         const float* __restrict__ w_lin,  // [1, H]
         const float* __restrict__ b_lin,  // [1]
         float* __restrict__ out)          // [2B]
{
    extern __shared__ char smem[];
    __shared__ __align__(8) uint64_t mbars[2 * NSTR];   // [stream][parity]
    const uint32_t sbase = smem_u32(smem);

    const int tid  = threadIdx.x;
    const int wid  = tid >> 5;
    const int lane = tid & 31;
    const int gw   = wid >> 2;         // stream 0..3
    const int oct  = wid & 3;          // unit octet within stream
    const int g    = lane >> 2;        // fragment row 0..7
    const int c    = lane & 3;         // fragment k-lane 0..3
    const int gtid = tid & 127;        // thread id within stream
    const int rank = blockIdx.x;       // cluster rank: units rank*32..+32
    const int bg   = blockIdx.y;       // batch group (rows bg*64..+64)

    // ---- zero all activation buffers (h(0)=0, pads clean) ----
    for (int e = tid; e < 2 * NSTR * ABUF / 4; e += NTH)
        *(uint32_t*)(smem + WBYTES + e * 4) = 0u;

    // ---- weights -> SMEM bf16, permuted. rows: chain*32+u; chains r,z,nh,nx ----
    for (int e = tid; e < WROWS * PB; e += NTH) {
        int row = e / PB, k = e - row * PB;
        int ch = row >> 5, u = row & 31, gu = rank * 32 + u;
        float v = 0.f;
        if (k < 320) {
            if (ch == 0) {
                v = (k < HDIM) ? w_hh[(size_t)gu * HDIM + k]
                               : w_ih[(size_t)gu * IDIM + (k - HDIM)];
            } else if (ch == 1) {
                int gr = HDIM + gu;
                v = (k < HDIM) ? w_hh[(size_t)gr * HDIM + k]
                               : w_ih[(size_t)gr * IDIM + (k - HDIM)];
            } else if (ch == 2) {
                if (k < HDIM) v = w_hh[(size_t)(2 * HDIM + gu) * HDIM + k];
            } else {
                if (k >= HDIM) v = w_ih[(size_t)(2 * HDIM + gu) * IDIM + (k - HDIM)];
            }
        }
        *(__nv_bfloat16*)(smem + row * ROWB + (k < 320 ? perm(k) : k) * 2) =
            __float2bfloat16(v);
    }

    // ---- per-thread biases for my 2 units (accumulator seeds) ----
    const int u0 = oct * 8 + 2 * c;
    float bR[2], bZ[2], bIN[2], bHN[2];
#pragma unroll
    for (int j = 0; j < 2; j++) {
        int gu = rank * 32 + u0 + j;
        bR[j]  = b_ih[gu] + b_hh[gu];
        bZ[j]  = b_ih[HDIM + gu] + b_hh[HDIM + gu];
        bIN[j] = b_ih[2 * HDIM + gu];
        bHN[j] = b_hh[2 * HDIM + gu];
    }

    // ---- stage x(0) into buffer [gw][0], slabs 16..19 ----
    const float* xgrp = x + (size_t)(bg * (NSTR * MTG) + gw * MTG) * XSTR;
    {
        const uint32_t b0 = WBYTES + (uint32_t)(gw * 2) * ABUF;
#pragma unroll
        for (int q = 0; q < 2; q++) {
            int fi = gtid + q * 128;
            int row = fi >> 4, c4 = fi & 15;
            int kb = 16 + (c4 >> 2), m = c4 & 3;
            float4 v = __ldg((const float4*)(xgrp + (size_t)row * XSTR + c4 * 4));
            char* slab = smem + b0 + kb * SLAB + row * 32;
            *(uint32_t*)(slab + pos16(4 * m))     = pack_bf16x2(v.x, v.y);
            *(uint32_t*)(slab + pos16(4 * m + 2)) = pack_bf16x2(v.z, v.w);
        }
    }
    if (tid == 0) {
#pragma unroll
        for (int i = 0; i < 2 * NSTR; i++) MBARRIER_INIT(smem_u32(&mbars[i]), 1);
    }
    __syncthreads();

    // ---- per-warp addresses ----
    const uint32_t abuf_s = sbase + WBYTES;
    const uint32_t aoff = (uint32_t)g * 32 + 8u * c;           // + bi*ABUF + kb*SLAB
    const uint32_t bR_a = sbase + (uint32_t)(oct * 8 + g) * ROWB + 8u * c;
    const uint32_t bZ_a = bR_a + 32u * ROWB;
    const uint32_t bH_a = bR_a + 64u * ROWB;
    const uint32_t bX_a = bR_a + 96u * ROWB;

    // ---- hoist nh weight fragments into registers (step-invariant) ----
    uint32_t wNH[16][2];
#pragma unroll
    for (int kb = 0; kb < 16; kb++) lds2(wNH[kb][0], wNH[kb][1], bH_a + kb * 32u);

    CLUSTER_SYNC();   // mbarriers + buffers visible cluster-wide before any bulk copy

    float hprev[4] = {0.f, 0.f, 0.f, 0.f};
    int ph[2] = {0, 0};
    const uint32_t mb_s = smem_u32(&mbars[gw * 2]);      // my stream's 2 mbars
    const int peer = (gtid < 7) ? (gtid < rank ? gtid : gtid + 1) : 0;
    const uint32_t myslab_off = (uint32_t)(2 * rank) * SLAB;
    const uint32_t est = ((u0 >> 4) ? SLAB : 0) + (uint32_t)g * 32 + (uint32_t)pos16(u0 & 15);

    // ---- precompute bulk-copy addresses for both parities (lanes gtid<7) ----
    uint32_t srcP[2], dstP[2], rmbP[2];
#pragma unroll
    for (int p2 = 0; p2 < 2; p2++) {
        srcP[p2] = sbase + WBYTES + (uint32_t)(gw * 2 + p2) * ABUF + myslab_off;
        dstP[p2] = mapa_u32(srcP[p2], peer);
        rmbP[p2] = mapa_u32(mb_s + 8u * p2, peer);
    }

#pragma unroll 1
    for (int t = 0; t < SEQT; ++t) {
        const uint32_t npar = (t + 1) & 1;
        const uint32_t nb_off = WBYTES + (uint32_t)(gw * 2 + npar) * ABUF;
        const uint32_t acur = abuf_s + (uint32_t)(gw * 2 + (t & 1)) * ABUF + aoff;
        const uint32_t lmb = mb_s + 8u * npar;

        // ---- early arm: expect_tx for the next phase (tx counts reconcile
        //      regardless of arm/delivery order; phase consumed at step t-1) ----
        if (gtid == 0) { MBARRIER_ARRIVE_EXPECT_TX(lmb, TXB); }

        // ---- stage x(t+1) (pre-wait; stream-local slabs, sequenced by last bar) ----
        if (t + 1 < SEQT) {
#pragma unroll
            for (int q = 0; q < 2; q++) {
                int fi = gtid + q * 128;
                int row = fi >> 4, c4 = fi & 15;
                int kb = 16 + (c4 >> 2), m = c4 & 3;
                float4 v = __ldg((const float4*)(xgrp + (size_t)row * XSTR
                                                 + (size_t)(t + 1) * IDIM + c4 * 4));
                char* slab = smem + nb_off + kb * SLAB + row * 32;
                *(uint32_t*)(slab + pos16(4 * m))     = pack_bf16x2(v.x, v.y);
                *(uint32_t*)(slab + pos16(4 * m + 2)) = pack_bf16x2(v.z, v.w);
            }
        }

        // ---- accumulators seeded with biases (replaces 16 epilogue FADDs) ----
        float dR[4], dZ[4], dH[4], dX[4];
#pragma unroll
        for (int i = 0; i < 4; i++) {
            int j = i & 1;
            dR[i] = bR[j]; dZ[i] = bZ[j]; dH[i] = bHN[j]; dX[i] = bIN[j];
        }

        // ---- pre-wait x-part MMA (kb 16..19; r,z,nx weights from smem) ----
#pragma unroll
        for (int kb = 16; kb < 20; kb++) {
            const uint32_t ao = acur + (uint32_t)kb * SLAB;
            const uint32_t wo = (uint32_t)kb * 32u;
            uint32_t a0, a2, a1, a3, r0, r1, z0, z1, n0, n1;
            lds2(a0, a2, ao);
            lds2(a1, a3, ao + 256);
            lds2(r0, r1, bR_a + wo);
            lds2(z0, z1, bZ_a + wo);
            lds2(n0, n1, bX_a + wo);
            mma16(dR, a0, a1, a2, a3, r0, r1);
            mma16(dZ, a0, a1, a2, a3, z0, z1);
            mma16(dX, a0, a1, a2, a3, n0, n1);
        }

        // ---- wait for h(t) ----
        if (t > 0) {
            int m = t & 1;
            MBARRIER_WAIT_PARITY(mb_s + 8u * m, ph[m]);
            ph[m] ^= 1;

            // ---- post-wait h-part MMA (kb 0..15) ----
#pragma unroll
            for (int kb = 0; kb < 16; kb++) {
                const uint32_t ao = acur + (uint32_t)kb * SLAB;
                const uint32_t wo = (uint32_t)kb * 32u;
                uint32_t a0, a2, a1, a3, r0, r1, z0, z1;
                lds2(a0, a2, ao);
                lds2(a1, a3, ao + 256);
                lds2(r0, r1, bR_a + wo);
                lds2(z0, z1, bZ_a + wo);
                mma16(dR, a0, a1, a2, a3, r0, r1);
                mma16(dZ, a0, a1, a2, a3, z0, z1);
                mma16(dH, a0, a1, a2, a3, wNH[kb][0], wNH[kb][1]);
            }
        }

        // ---- gate epilogue (register-local; biases pre-seeded) ----
        float hn[4];
#pragma unroll
        for (int i = 0; i < 4; i++) {
            float r = sig_ap(dR[i]);
            float z = sig_ap(dZ[i]);
            float n = tanh_acc(fmaf(r, dH[i], dX[i]));
            hn[i] = fmaf(z, hprev[i] - n, n);
            hprev[i] = hn[i];
        }

        // ---- local STS of my h slab block, stream barrier ----
        {
            char* dst = smem + nb_off + myslab_off + est;
            *(uint32_t*)(dst)       = pack_bf16x2(hn[0], hn[1]);   // row g
            *(uint32_t*)(dst + 256) = pack_bf16x2(hn[2], hn[3]);   // row g+8
        }
        STREAM_BAR(1 + gw);

        // ---- exchange: 7 bulk copies (1KB each); single arrival (tx-chain safety) ----
        if (gtid < 7) {
            asm volatile("fence.proxy.async.shared::cta;" ::: "memory");
            bulk_to_peer(dstP[npar], srcP[npar], 1024u, rmbP[npar]);
        }
    }

    // ---- final wait: h(512) fully delivered into buffer [gw][0] ----
    MBARRIER_WAIT_PARITY(mb_s, ph[0]);

    // ---- head (rank 0): p = sigmoid(h_last . w_lin + b_lin); out = [p, 1-p] ----
    if (rank == 0) {
        const int row = gtid >> 3, seg = gtid & 7;
        const uint32_t hb = WBYTES + (uint32_t)(gw * 2) * ABUF;
        float s = 0.f;
#pragma unroll
        for (int kk = 0; kk < 32; kk++) {
            int k = seg * 32 + kk;
            const char* p8 = smem + hb + (k >> 4) * SLAB + row * 32 + pos16(k & 15);
            float hv = __bfloat162float(*(const __nv_bfloat16*)p8);
            s = fmaf(hv, __ldg(w_lin + k), s);
        }
        s += __shfl_xor_sync(0xffffffffu, s, 1);
        s += __shfl_xor_sync(0xffffffffu, s, 2);
        s += __shfl_xor_sync(0xffffffffu, s, 4);
        if (seg == 0) {
            float p = sigf(s + __ldg(b_lin));   // head sigmoid stays exact
            int gb = bg * (NSTR * MTG) + gw * MTG + row;
            out[2 * gb]     = p;
            out[2 * gb + 1] = 1.f - p;
        }
    }

    CLUSTER_SYNC();   // no CTA exits while peers may still target its SMEM
}

extern "C" void kernel_launch(void* const* d_in, const int* in_sizes, int n_in,
                              void* d_out, int out_size) {
    const float* x     = (const float*)d_in[0];
    const float* w_ih0 = (const float*)d_in[1];
    const float* w_hh0 = (const float*)d_in[2];
    const float* b_ih0 = (const float*)d_in[3];
    const float* b_hh0 = (const float*)d_in[4];
    // d_in[5..8]: layer-1 GRU weights — dead code (output uses layer-0 h_last only)
    const float* w_lin = (const float*)d_in[9];
    const float* b_lin = (const float*)d_in[10];
    float* out = (float*)d_out;

    cudaFuncSetAttribute(gru_tune, cudaFuncAttributeMaxDynamicSharedMemorySize, SMEMSZ);

    dim3 grid(CLUSTER, NBG);   // 8 x 8 = 64 CTAs = 8 clusters of 8, 4 streams each
    gru_tune<<<grid, NTH, SMEMSZ>>>(x, w_ih0, w_hh0, b_ih0, b_hh0, w_lin, b_lin, out);
}

// round 17
// speedup vs baseline: 1.2996x; 1.0342x over previous
#include <cuda_runtime.h>
#include <cuda_bf16.h>
#include <cstdint>

// ---------------- problem dims ----------------
#define SEQT  512
#define IDIM  64
#define HDIM  256
#define XSTR  ((size_t)SEQT * IDIM)

// ---------------- tiling ----------------
#define CLUSTER 8        // CTAs per cluster: each owns 32 hidden units
#define NBG     8        // batch groups (clusters); 64 rows each = 4 streams x 16
#define NSTR    4        // independent recurrence streams per CTA
#define MTG     16       // batch rows per stream
#define NTH     512      // 16 warps: 4 per stream
#define PB      336      // weight row pitch in bf16 (336 % 64 == 16 -> conflict-free)
#define ROWB    (PB * 2) // 672 bytes per weight row
#define WROWS   128      // gate rows per CTA: 4 chains (r,z,nh,nx) x 32 units
#define WBYTES  (WROWS * ROWB)          // 86016 (multiple of 512)
#define SLAB    512
#define ABUF    (20 * SLAB)             // 10240 per [stream][parity] buffer
#define SMEMSZ  (WBYTES + 2 * NSTR * ABUF)   // 167936
#define TXB     (7 * 1024)              // bulk-tx bytes expected per stream phase

// within-16-col fragment order: elem e -> byte offset in a 32B row
__device__ __forceinline__ int pos16(int e) {
    return ((e >> 1) & 3) * 8 + ((e >> 3) << 2) + (e & 1) * 2;
}
// weight-side perm across full k (same order per 16-block)
__device__ __forceinline__ int perm(int k) {
    int j = k & 15;
    return (k & ~15) + ((j >> 1) & 3) * 4 + ((j >> 3) << 1) + (j & 1);
}

// MUFU tanh (1 op)
__device__ __forceinline__ float tanh_ap(float v) {
    float y;
    asm("tanh.approx.f32 %0, %1;" : "=f"(y) : "f"(v));
    return y;
}
// r,z gates: sigmoid via MUFU tanh (1 MUFU + 2 FMA)
__device__ __forceinline__ float sig_ap(float v) {
    return fmaf(tanh_ap(0.5f * v), 0.5f, 0.5f);
}
__device__ __forceinline__ float sigf(float v) { return 1.0f / (1.0f + __expf(-v)); }

__device__ __forceinline__ uint32_t smem_u32(const void* p) {
    uint32_t a;
    asm("{ .reg .u64 t; cvta.to.shared.u64 t, %1; cvt.u32.u64 %0, t; }" : "=r"(a) : "l"(p));
    return a;
}
__device__ __forceinline__ uint32_t pack_bf16x2(float lo, float hi) {
    uint32_t r;
    asm("cvt.rn.bf16x2.f32 %0, %1, %2;" : "=r"(r) : "f"(hi), "f"(lo));
    return r;
}
__device__ __forceinline__ void lds2(uint32_t& x, uint32_t& y, uint32_t addr) {
    asm volatile("ld.shared.v2.b32 {%0, %1}, [%2];" : "=r"(x), "=r"(y) : "r"(addr));
}
__device__ __forceinline__ uint32_t mapa_u32(uint32_t laddr, int rank) {
    uint32_t r;
    asm("mapa.shared::cluster.u32 %0, %1, %2;" : "=r"(r) : "r"(laddr), "r"(rank));
    return r;
}
__device__ __forceinline__ void bulk_to_peer(uint32_t dst_cluster, uint32_t src_cta,
                                             uint32_t bytes, uint32_t rmbar) {
    asm volatile("cp.async.bulk.shared::cluster.shared::cta.mbarrier::complete_tx::bytes "
                 "[%0], [%1], %2, [%3];"
                 :: "r"(dst_cluster), "r"(src_cta), "r"(bytes), "r"(rmbar) : "memory");
}
#define MBARRIER_INIT(mb, c) \
    asm volatile("mbarrier.init.shared.b64 [%0], %1;" \
                 :: "r"((uint32_t)(mb)), "r"((uint32_t)(c)) : "memory")
#define MBARRIER_ARRIVE_EXPECT_TX(mb, n) \
    asm volatile("mbarrier.arrive.expect_tx.shared.b64 _, [%0], %1;" \
                 :: "r"((uint32_t)(mb)), "r"((uint32_t)(n)) : "memory")
#define MBARRIER_WAIT_PARITY(mb, par) do { \
    uint32_t _m = (uint32_t)(mb), _p = (uint32_t)(par), _d; \
    asm volatile("{\n\t.reg .pred p;\n\t" \
        "mbarrier.try_wait.parity.acquire.cta.shared::cta.b64 p, [%1], %2;\n\t" \
        "selp.b32 %0, 1, 0, p;\n\t}" : "=r"(_d) : "r"(_m), "r"(_p) : "memory"); \
    if (!_d) { \
        asm volatile("{\n\t.reg .pred P1;\n\t" \
            "WL_%=:\n\t" \
            "mbarrier.try_wait.parity.acquire.cta.shared::cta.b64 P1, [%0], %1, 0x989680;\n\t" \
            "@P1 bra.uni WD_%=;\n\tbra.uni WL_%=;\n\tWD_%=:\n\t}" \
            :: "r"(_m), "r"(_p) : "memory"); \
    } } while (0)
#define CLUSTER_SYNC() do { \
    asm volatile("barrier.cluster.arrive.aligned;" ::: "memory"); \
    asm volatile("barrier.cluster.wait.aligned;"   ::: "memory"); } while (0)
#define STREAM_BAR(id) \
    asm volatile("bar.sync %0, 128;" :: "r"(id) : "memory")

// D += A(16x16) * B(16x8)^T, bf16 -> f32
__device__ __forceinline__ void mma16(float* d, uint32_t a0, uint32_t a1, uint32_t a2,
                                      uint32_t a3, uint32_t b0, uint32_t b1) {
    asm volatile(
        "mma.sync.aligned.m16n8k16.row.col.f32.bf16.bf16.f32 "
        "{%0,%1,%2,%3}, {%4,%5,%6,%7}, {%8,%9}, {%0,%1,%2,%3};"
        : "+f"(d[0]), "+f"(d[1]), "+f"(d[2]), "+f"(d[3])
        : "r"(a0), "r"(a1), "r"(a2), "r"(a3), "r"(b0), "r"(b1));
}

__global__ void __launch_bounds__(NTH, 1) __cluster_dims__(CLUSTER, 1, 1)
gru_mufu(const float* __restrict__ x,      // [B, T, I]
         const float* __restrict__ w_ih,   // [3H, I]
         const float* __restrict__ w_hh,   // [3H, H]
         const float* __restrict__ b_ih,   // [3H]
         const float* __restrict__ b_hh,   // [3H]
         const float* __restrict__ w_lin,  // [1, H]
         const float* __restrict__ b_lin,  // [1]
         float* __restrict__ out)          // [2B]
{
    extern __shared__ char smem[];
    __shared__ __align__(8) uint64_t mbars[2 * NSTR];   // [stream][parity]
    const uint32_t sbase = smem_u32(smem);

    const int tid  = threadIdx.x;
    const int wid  = tid >> 5;
    const int lane = tid & 31;
    const int gw   = wid >> 2;         // stream 0..3
    const int oct  = wid & 3;          // unit octet within stream
    const int g    = lane >> 2;        // fragment row 0..7
    const int c    = lane & 3;         // fragment k-lane 0..3
    const int gtid = tid & 127;        // thread id within stream
    const int rank = blockIdx.x;       // cluster rank: units rank*32..+32
    const int bg   = blockIdx.y;       // batch group (rows bg*64..+64)

    // ---- zero all activation buffers (h(0)=0, pads clean) ----
    for (int e = tid; e < 2 * NSTR * ABUF / 4; e += NTH)
        *(uint32_t*)(smem + WBYTES + e * 4) = 0u;

    // ---- weights -> SMEM bf16, permuted. rows: chain*32+u; chains r,z,nh,nx ----
    for (int e = tid; e < WROWS * PB; e += NTH) {
        int row = e / PB, k = e - row * PB;
        int ch = row >> 5, u = row & 31, gu = rank * 32 + u;
        float v = 0.f;
        if (k < 320) {
            if (ch == 0) {
                v = (k < HDIM) ? w_hh[(size_t)gu * HDIM + k]
                               : w_ih[(size_t)gu * IDIM + (k - HDIM)];
            } else if (ch == 1) {
                int gr = HDIM + gu;
                v = (k < HDIM) ? w_hh[(size_t)gr * HDIM + k]
                               : w_ih[(size_t)gr * IDIM + (k - HDIM)];
            } else if (ch == 2) {
                if (k < HDIM) v = w_hh[(size_t)(2 * HDIM + gu) * HDIM + k];
            } else {
                if (k >= HDIM) v = w_ih[(size_t)(2 * HDIM + gu) * IDIM + (k - HDIM)];
            }
        }
        *(__nv_bfloat16*)(smem + row * ROWB + (k < 320 ? perm(k) : k) * 2) =
            __float2bfloat16(v);
    }

    // ---- per-thread biases for my 2 units (accumulator seeds) ----
    const int u0 = oct * 8 + 2 * c;
    float bR[2], bZ[2], bIN[2], bHN[2];
#pragma unroll
    for (int j = 0; j < 2; j++) {
        int gu = rank * 32 + u0 + j;
        bR[j]  = b_ih[gu] + b_hh[gu];
        bZ[j]  = b_ih[HDIM + gu] + b_hh[HDIM + gu];
        bIN[j] = b_ih[2 * HDIM + gu];
        bHN[j] = b_hh[2 * HDIM + gu];
    }

    // ---- stage x(0) into buffer [gw][0], slabs 16..19 ----
    const float* xgrp = x + (size_t)(bg * (NSTR * MTG) + gw * MTG) * XSTR;
    {
        const uint32_t b0 = WBYTES + (uint32_t)(gw * 2) * ABUF;
#pragma unroll
        for (int q = 0; q < 2; q++) {
            int fi = gtid + q * 128;
            int row = fi >> 4, c4 = fi & 15;
            int kb = 16 + (c4 >> 2), m = c4 & 3;
            float4 v = __ldg((const float4*)(xgrp + (size_t)row * XSTR + c4 * 4));
            char* slab = smem + b0 + kb * SLAB + row * 32;
            *(uint32_t*)(slab + pos16(4 * m))     = pack_bf16x2(v.x, v.y);
            *(uint32_t*)(slab + pos16(4 * m + 2)) = pack_bf16x2(v.z, v.w);
        }
    }
    if (tid == 0) {
#pragma unroll
        for (int i = 0; i < 2 * NSTR; i++) MBARRIER_INIT(smem_u32(&mbars[i]), 1);
    }
    __syncthreads();

    // ---- per-warp addresses ----
    const uint32_t abuf_s = sbase + WBYTES;
    const uint32_t aoff = (uint32_t)g * 32 + 8u * c;           // + bi*ABUF + kb*SLAB
    const uint32_t bR_a = sbase + (uint32_t)(oct * 8 + g) * ROWB + 8u * c;
    const uint32_t bZ_a = bR_a + 32u * ROWB;
    const uint32_t bH_a = bR_a + 64u * ROWB;
    const uint32_t bX_a = bR_a + 96u * ROWB;

    // ---- hoist nh weight fragments into registers (step-invariant) ----
    uint32_t wNH[16][2];
#pragma unroll
    for (int kb = 0; kb < 16; kb++) lds2(wNH[kb][0], wNH[kb][1], bH_a + kb * 32u);

    CLUSTER_SYNC();   // mbarriers + buffers visible cluster-wide before any bulk copy

    float hprev[4] = {0.f, 0.f, 0.f, 0.f};
    int ph[2] = {0, 0};
    const uint32_t mb_s = smem_u32(&mbars[gw * 2]);      // my stream's 2 mbars
    const int peer = (gtid < 7) ? (gtid < rank ? gtid : gtid + 1) : 0;
    const uint32_t myslab_off = (uint32_t)(2 * rank) * SLAB;
    const uint32_t est = ((u0 >> 4) ? SLAB : 0) + (uint32_t)g * 32 + (uint32_t)pos16(u0 & 15);

    // ---- precompute bulk-copy addresses for both parities (lanes gtid<7) ----
    uint32_t srcP[2], dstP[2], rmbP[2];
#pragma unroll
    for (int p2 = 0; p2 < 2; p2++) {
        srcP[p2] = sbase + WBYTES + (uint32_t)(gw * 2 + p2) * ABUF + myslab_off;
        dstP[p2] = mapa_u32(srcP[p2], peer);
        rmbP[p2] = mapa_u32(mb_s + 8u * p2, peer);
    }

#pragma unroll 1
    for (int t = 0; t < SEQT; ++t) {
        const uint32_t npar = (t + 1) & 1;
        const uint32_t nb_off = WBYTES + (uint32_t)(gw * 2 + npar) * ABUF;
        const uint32_t acur = abuf_s + (uint32_t)(gw * 2 + (t & 1)) * ABUF + aoff;
        const uint32_t lmb = mb_s + 8u * npar;

        // ---- early arm: expect_tx for the next phase ----
        if (gtid == 0) { MBARRIER_ARRIVE_EXPECT_TX(lmb, TXB); }

        // ---- stage x(t+1) (pre-wait; stream-local slabs, sequenced by last bar) ----
        if (t + 1 < SEQT) {
#pragma unroll
            for (int q = 0; q < 2; q++) {
                int fi = gtid + q * 128;
                int row = fi >> 4, c4 = fi & 15;
                int kb = 16 + (c4 >> 2), m = c4 & 3;
                float4 v = __ldg((const float4*)(xgrp + (size_t)row * XSTR
                                                 + (size_t)(t + 1) * IDIM + c4 * 4));
                char* slab = smem + nb_off + kb * SLAB + row * 32;
                *(uint32_t*)(slab + pos16(4 * m))     = pack_bf16x2(v.x, v.y);
                *(uint32_t*)(slab + pos16(4 * m + 2)) = pack_bf16x2(v.z, v.w);
            }
        }

        // ---- accumulators seeded with biases ----
        float dR[4], dZ[4], dH[4], dX[4];
#pragma unroll
        for (int i = 0; i < 4; i++) {
            int j = i & 1;
            dR[i] = bR[j]; dZ[i] = bZ[j]; dH[i] = bHN[j]; dX[i] = bIN[j];
        }

        // ---- pre-wait x-part MMA (kb 16..19; r,z,nx weights from smem) ----
#pragma unroll
        for (int kb = 16; kb < 20; kb++) {
            const uint32_t ao = acur + (uint32_t)kb * SLAB;
            const uint32_t wo = (uint32_t)kb * 32u;
            uint32_t a0, a2, a1, a3, r0, r1, z0, z1, n0, n1;
            lds2(a0, a2, ao);
            lds2(a1, a3, ao + 256);
            lds2(r0, r1, bR_a + wo);
            lds2(z0, z1, bZ_a + wo);
            lds2(n0, n1, bX_a + wo);
            mma16(dR, a0, a1, a2, a3, r0, r1);
            mma16(dZ, a0, a1, a2, a3, z0, z1);
            mma16(dX, a0, a1, a2, a3, n0, n1);
        }

        // ---- wait for h(t) ----
        if (t > 0) {
            int m = t & 1;
            MBARRIER_WAIT_PARITY(mb_s + 8u * m, ph[m]);
            ph[m] ^= 1;

            // ---- post-wait h-part MMA (kb 0..15) ----
#pragma unroll
            for (int kb = 0; kb < 16; kb++) {
                const uint32_t ao = acur + (uint32_t)kb * SLAB;
                const uint32_t wo = (uint32_t)kb * 32u;
                uint32_t a0, a2, a1, a3, r0, r1, z0, z1;
                lds2(a0, a2, ao);
                lds2(a1, a3, ao + 256);
                lds2(r0, r1, bR_a + wo);
                lds2(z0, z1, bZ_a + wo);
                mma16(dR, a0, a1, a2, a3, r0, r1);
                mma16(dZ, a0, a1, a2, a3, z0, z1);
                mma16(dH, a0, a1, a2, a3, wNH[kb][0], wNH[kb][1]);
            }
        }

        // ---- gate epilogue: all-MUFU activations (12 MUFU/thread/step) ----
        float hn[4];
#pragma unroll
        for (int i = 0; i < 4; i++) {
            float r = sig_ap(dR[i]);
            float z = sig_ap(dZ[i]);
            float n = tanh_ap(fmaf(r, dH[i], dX[i]));
            hn[i] = fmaf(z, hprev[i] - n, n);
            hprev[i] = hn[i];
        }

        // ---- local STS of my h slab block, stream barrier ----
        {
            char* dst = smem + nb_off + myslab_off + est;
            *(uint32_t*)(dst)       = pack_bf16x2(hn[0], hn[1]);   // row g
            *(uint32_t*)(dst + 256) = pack_bf16x2(hn[2], hn[3]);   // row g+8
        }
        STREAM_BAR(1 + gw);

        // ---- exchange: 7 bulk copies (1KB each); single arrival (tx-chain safety) ----
        if (gtid < 7) {
            asm volatile("fence.proxy.async.shared::cta;" ::: "memory");
            bulk_to_peer(dstP[npar], srcP[npar], 1024u, rmbP[npar]);
        }
    }

    // ---- final wait: h(512) fully delivered into buffer [gw][0] ----
    MBARRIER_WAIT_PARITY(mb_s, ph[0]);

    // ---- head (rank 0): p = sigmoid(h_last . w_lin + b_lin); out = [p, 1-p] ----
    if (rank == 0) {
        const int row = gtid >> 3, seg = gtid & 7;
        const uint32_t hb = WBYTES + (uint32_t)(gw * 2) * ABUF;
        float s = 0.f;
#pragma unroll
        for (int kk = 0; kk < 32; kk++) {
            int k = seg * 32 + kk;
            const char* p8 = smem + hb + (k >> 4) * SLAB + row * 32 + pos16(k & 15);
            float hv = __bfloat162float(*(const __nv_bfloat16*)p8);
            s = fmaf(hv, __ldg(w_lin + k), s);
        }
        s += __shfl_xor_sync(0xffffffffu, s, 1);
        s += __shfl_xor_sync(0xffffffffu, s, 2);
        s += __shfl_xor_sync(0xffffffffu, s, 4);
        if (seg == 0) {
            float p = sigf(s + __ldg(b_lin));   // head sigmoid stays exact
            int gb = bg * (NSTR * MTG) + gw * MTG + row;
            out[2 * gb]     = p;
            out[2 * gb + 1] = 1.f - p;
        }
    }

    CLUSTER_SYNC();   // no CTA exits while peers may still target its SMEM
}

extern "C" void kernel_launch(void* const* d_in, const int* in_sizes, int n_in,
                              void* d_out, int out_size) {
    const float* x     = (const float*)d_in[0];
    const float* w_ih0 = (const float*)d_in[1];
    const float* w_hh0 = (const float*)d_in[2];
    const float* b_ih0 = (const float*)d_in[3];
    const float* b_hh0 = (const float*)d_in[4];
    // d_in[5..8]: layer-1 GRU weights — dead code (output uses layer-0 h_last only)
    const float* w_lin = (const float*)d_in[9];
    const float* b_lin = (const float*)d_in[10];
    float* out = (float*)d_out;

    cudaFuncSetAttribute(gru_mufu, cudaFuncAttributeMaxDynamicSharedMemorySize, SMEMSZ);

    dim3 grid(CLUSTER, NBG);   // 8 x 8 = 64 CTAs = 8 clusters of 8, 4 streams each
    gru_mufu<<<grid, NTH, SMEMSZ>>>(x, w_ih0, w_hh0, b_ih0, b_hh0, w_lin, b_lin, out);
}